// round 1
// baseline (speedup 1.0000x reference)
#include <cuda_runtime.h>

// ---------------------------------------------------------------------------
// NonLocal2dBlock: y = gamma * out_conv( att @ g_pool^T ) + x
//   theta = conv1x1(x, theta_w)                (B, 32, 4096)
//   phi   = maxpool2(conv1x1(x, phi_w))        (B, 32, 1024)
//   g     = maxpool2(conv1x1(x, g_w))          (B, 128, 1024)
//   E     = theta^T @ phi                      (B, 4096, 1024)
//   P     = softmax(E, axis=-1)
//   AV    = g @ P^T                            (B, 128, 4096)
//   y     = gamma * (out_w @ AV + out_b) + x   (B, 256, 4096)
// ---------------------------------------------------------------------------

namespace {
constexpr int B_ = 8, C_ = 256, H_ = 64, W_ = 64;
constexpr int NPIX = H_ * W_;          // 4096
constexpr int MP   = (H_/2) * (W_/2);  // 1024
constexpr int D_   = 32, DV = 128;
constexpr int CHCAT = D_ + D_ + DV;    // 192
}

// scratch (device globals: no allocation allowed in kernel_launch)
__device__ float d_Wcat[CHCAT * C_];
__device__ float d_bcat[CHCAT];
__device__ float d_conv[(size_t)B_ * CHCAT * NPIX];   // theta | phi_full | g_full
__device__ float d_phip[(size_t)B_ * D_ * MP];
__device__ float d_gp  [(size_t)B_ * DV * MP];
__device__ float d_att [(size_t)B_ * NPIX * MP];      // energy -> attention in place
__device__ float d_av  [(size_t)B_ * DV * NPIX];

// ---------------------------------------------------------------------------
__global__ void prep_weights(const float* __restrict__ tw, const float* __restrict__ tb,
                             const float* __restrict__ pw, const float* __restrict__ pb,
                             const float* __restrict__ gw, const float* __restrict__ gb)
{
    int i = blockIdx.x * blockDim.x + threadIdx.x;
    if (i < CHCAT * C_) {
        int ch = i / C_, k = i % C_;
        float v;
        if      (ch < D_)     v = tw[ch * C_ + k];
        else if (ch < 2 * D_) v = pw[(ch - D_) * C_ + k];
        else                  v = gw[(ch - 2 * D_) * C_ + k];
        d_Wcat[i] = v;
    }
    if (i < CHCAT) {
        float v;
        if      (i < D_)     v = tb[i];
        else if (i < 2 * D_) v = pb[i - D_];
        else                 v = gb[i - 2 * D_];
        d_bcat[i] = v;
    }
}

// ---------------------------------------------------------------------------
// Generic 64x64 tiled fp32 GEMM, BK=16, 256 threads, 4x4 microtile.
//   C[M][N] = A x B     (per batch z, element strides sA/sB/sC)
// AKM = 0: A stored [M][K] (k contiguous);  AKM = 1: A stored [K][M] (m contiguous)
// BNK = 0: B stored [K][N] (n contiguous);  BNK = 1: B stored [N][K] (k contiguous)
// EPI = 0: store;  1: +bias[m];  2: gamma*(acc+bias[m]) + resid[m][n]
// All dims assumed multiples of tile sizes (true for this problem).
// ---------------------------------------------------------------------------
template<int AKM, int BNK, int EPI>
__global__ __launch_bounds__(256)
void gemm_k(const float* __restrict__ A, const float* __restrict__ B,
            float* __restrict__ C,
            int Mdim, int Ndim, int Kdim,
            long long sA, long long sB, long long sC,
            const float* __restrict__ bias,
            const float* __restrict__ gamma,
            const float* __restrict__ resid, long long sR)
{
    __shared__ float As[16][68];
    __shared__ float Bs[16][68];

    int bz = blockIdx.z;
    A += (size_t)bz * sA;
    B += (size_t)bz * sB;
    C += (size_t)bz * sC;
    if (EPI == 2) resid += (size_t)bz * sR;

    int tid = threadIdx.x;
    int tx = tid & 15, ty = tid >> 4;
    int m0 = blockIdx.y * 64, n0 = blockIdx.x * 64;

    int ltc = tid & 3,  ltr = tid >> 2;   // K-minor loads (4 float4 per 16-wide row)
    int lkm = tid >> 4, ltm = tid & 15;   // M/N-minor loads (16 float4 per 64-wide row)

    float acc[4][4];
#pragma unroll
    for (int i = 0; i < 4; i++)
#pragma unroll
        for (int j = 0; j < 4; j++) acc[i][j] = 0.f;

    for (int k0 = 0; k0 < Kdim; k0 += 16) {
        if (AKM == 0) {
            float4 v = *(const float4*)(A + (size_t)(m0 + ltr) * Kdim + k0 + ltc * 4);
            As[ltc*4+0][ltr] = v.x; As[ltc*4+1][ltr] = v.y;
            As[ltc*4+2][ltr] = v.z; As[ltc*4+3][ltr] = v.w;
        } else {
            *(float4*)&As[lkm][ltm*4] =
                *(const float4*)(A + (size_t)(k0 + lkm) * Mdim + m0 + ltm * 4);
        }
        if (BNK == 0) {
            *(float4*)&Bs[lkm][ltm*4] =
                *(const float4*)(B + (size_t)(k0 + lkm) * Ndim + n0 + ltm * 4);
        } else {
            float4 v = *(const float4*)(B + (size_t)(n0 + ltr) * Kdim + k0 + ltc * 4);
            Bs[ltc*4+0][ltr] = v.x; Bs[ltc*4+1][ltr] = v.y;
            Bs[ltc*4+2][ltr] = v.z; Bs[ltc*4+3][ltr] = v.w;
        }
        __syncthreads();
#pragma unroll
        for (int k = 0; k < 16; k++) {
            float4 a = *(const float4*)&As[k][ty * 4];
            float4 b = *(const float4*)&Bs[k][tx * 4];
            acc[0][0] += a.x*b.x; acc[0][1] += a.x*b.y; acc[0][2] += a.x*b.z; acc[0][3] += a.x*b.w;
            acc[1][0] += a.y*b.x; acc[1][1] += a.y*b.y; acc[1][2] += a.y*b.z; acc[1][3] += a.y*b.w;
            acc[2][0] += a.z*b.x; acc[2][1] += a.z*b.y; acc[2][2] += a.z*b.z; acc[2][3] += a.z*b.w;
            acc[3][0] += a.w*b.x; acc[3][1] += a.w*b.y; acc[3][2] += a.w*b.z; acc[3][3] += a.w*b.w;
        }
        __syncthreads();
    }

    float gm = 0.f;
    if (EPI == 2) gm = __ldg(gamma);
#pragma unroll
    for (int i = 0; i < 4; i++) {
        int m = m0 + ty * 4 + i;
        float4 r = make_float4(acc[i][0], acc[i][1], acc[i][2], acc[i][3]);
        if (EPI >= 1) {
            float bv = __ldg(&bias[m]);
            r.x += bv; r.y += bv; r.z += bv; r.w += bv;
        }
        if (EPI == 2) {
            float4 xr = *(const float4*)(resid + (size_t)m * Ndim + n0 + tx * 4);
            r.x = gm * r.x + xr.x; r.y = gm * r.y + xr.y;
            r.z = gm * r.z + xr.z; r.w = gm * r.w + xr.w;
        }
        *(float4*)(C + (size_t)m * Ndim + n0 + tx * 4) = r;
    }
}

// ---------------------------------------------------------------------------
// 2x2 maxpool of phi_full / g_full slices of d_conv -> d_phip / d_gp
// ---------------------------------------------------------------------------
__global__ void pool_kernel()
{
    int i = blockIdx.x * blockDim.x + threadIdx.x;
    constexpr int total = B_ * (D_ + DV) * MP;
    if (i >= total) return;
    int m  = i % MP;
    int r  = i / MP;
    int ch = r % (D_ + DV);
    int b  = r / (D_ + DV);
    int mh = m >> 5, mw = m & 31;
    const float* src; float* dst;
    if (ch < D_) {
        src = d_conv + ((size_t)b * CHCAT + D_ + ch) * NPIX;
        dst = d_phip + ((size_t)b * D_ + ch) * MP;
    } else {
        src = d_conv + ((size_t)b * CHCAT + 2 * D_ + (ch - D_)) * NPIX;
        dst = d_gp   + ((size_t)b * DV + (ch - D_)) * MP;
    }
    int p0 = (mh * 2) * W_ + mw * 2;
    float v = fmaxf(fmaxf(src[p0], src[p0 + 1]),
                    fmaxf(src[p0 + W_], src[p0 + W_ + 1]));
    dst[m] = v;
}

// ---------------------------------------------------------------------------
// Row softmax over M=1024, in place on d_att. One 128-thread block per row.
// ---------------------------------------------------------------------------
__global__ __launch_bounds__(128)
void softmax_kernel()
{
    float* p = d_att + (size_t)blockIdx.x * MP;
    int t = threadIdx.x;
    float4* pv = (float4*)p;
    float4 v0 = pv[t];
    float4 v1 = pv[t + 128];

    float m = fmaxf(fmaxf(fmaxf(v0.x, v0.y), fmaxf(v0.z, v0.w)),
                    fmaxf(fmaxf(v1.x, v1.y), fmaxf(v1.z, v1.w)));
#pragma unroll
    for (int o = 16; o; o >>= 1) m = fmaxf(m, __shfl_xor_sync(0xffffffffu, m, o));
    __shared__ float redm[4], reds[4];
    if ((t & 31) == 0) redm[t >> 5] = m;
    __syncthreads();
    m = fmaxf(fmaxf(redm[0], redm[1]), fmaxf(redm[2], redm[3]));

    v0.x = __expf(v0.x - m); v0.y = __expf(v0.y - m);
    v0.z = __expf(v0.z - m); v0.w = __expf(v0.w - m);
    v1.x = __expf(v1.x - m); v1.y = __expf(v1.y - m);
    v1.z = __expf(v1.z - m); v1.w = __expf(v1.w - m);

    float s = v0.x + v0.y + v0.z + v0.w + v1.x + v1.y + v1.z + v1.w;
#pragma unroll
    for (int o = 16; o; o >>= 1) s += __shfl_xor_sync(0xffffffffu, s, o);
    if ((t & 31) == 0) reds[t >> 5] = s;
    __syncthreads();
    s = reds[0] + reds[1] + reds[2] + reds[3];

    float inv = 1.f / s;
    v0.x *= inv; v0.y *= inv; v0.z *= inv; v0.w *= inv;
    v1.x *= inv; v1.y *= inv; v1.z *= inv; v1.w *= inv;
    pv[t] = v0;
    pv[t + 128] = v1;
}

// ---------------------------------------------------------------------------
extern "C" void kernel_launch(void* const* d_in, const int* in_sizes, int n_in,
                              void* d_out, int out_size)
{
    const float* x     = (const float*)d_in[0];
    const float* tw    = (const float*)d_in[1];
    const float* tb    = (const float*)d_in[2];
    const float* pw    = (const float*)d_in[3];
    const float* pb    = (const float*)d_in[4];
    const float* gw    = (const float*)d_in[5];
    const float* gb    = (const float*)d_in[6];
    const float* ow    = (const float*)d_in[7];
    const float* ob    = (const float*)d_in[8];
    const float* gamma = (const float*)d_in[9];
    float* out = (float*)d_out;

    float *pWcat, *pbcat, *pconv, *pphip, *pgp, *patt, *pav;
    cudaGetSymbolAddress((void**)&pWcat, d_Wcat);
    cudaGetSymbolAddress((void**)&pbcat, d_bcat);
    cudaGetSymbolAddress((void**)&pconv, d_conv);
    cudaGetSymbolAddress((void**)&pphip, d_phip);
    cudaGetSymbolAddress((void**)&pgp,   d_gp);
    cudaGetSymbolAddress((void**)&patt,  d_att);
    cudaGetSymbolAddress((void**)&pav,   d_av);

    // K0: pack concatenated QKV weights/biases
    prep_weights<<<(CHCAT * C_ + 255) / 256, 256>>>(tw, tb, pw, pb, gw, gb);

    // K1: fused QKV conv1x1 GEMM  [192x256] @ [256x4096] -> d_conv
    {
        dim3 g(NPIX / 64, CHCAT / 64, B_);
        gemm_k<0, 0, 1><<<g, 256>>>(pWcat, x, pconv,
                                    CHCAT, NPIX, C_,
                                    0LL, (long long)C_ * NPIX, (long long)CHCAT * NPIX,
                                    pbcat, nullptr, nullptr, 0LL);
    }

    // K2: 2x2 maxpool of phi / g
    {
        int tot = B_ * (D_ + DV) * MP;
        pool_kernel<<<(tot + 255) / 256, 256>>>();
    }

    // K3: energy E[4096x1024] = theta^T @ phi_p   (A is [K=32][M=4096] K-major)
    {
        dim3 g(MP / 64, NPIX / 64, B_);
        gemm_k<1, 0, 0><<<g, 256>>>(pconv, pphip, patt,
                                    NPIX, MP, D_,
                                    (long long)CHCAT * NPIX, (long long)D_ * MP,
                                    (long long)NPIX * MP,
                                    nullptr, nullptr, nullptr, 0LL);
    }

    // K4: softmax rows (in place)
    softmax_kernel<<<B_ * NPIX, 128>>>();

    // K5: AV[128x4096] = g_p[128x1024] @ P^T   (B is [N=4096][K=1024])
    {
        dim3 g(NPIX / 64, DV / 64, B_);
        gemm_k<0, 1, 0><<<g, 256>>>(pgp, patt, pav,
                                    DV, NPIX, MP,
                                    (long long)DV * MP, (long long)NPIX * MP,
                                    (long long)DV * NPIX,
                                    nullptr, nullptr, nullptr, 0LL);
    }

    // K6: y = gamma*(out_w @ AV + out_b) + x
    {
        dim3 g(NPIX / 64, C_ / 64, B_);
        gemm_k<0, 0, 2><<<g, 256>>>(ow, pav, out,
                                    C_, NPIX, DV,
                                    0LL, (long long)DV * NPIX, (long long)C_ * NPIX,
                                    ob, gamma, x, (long long)C_ * NPIX);
    }
}

// round 7
// speedup vs baseline: 1.8120x; 1.8120x over previous
#include <cuda_runtime.h>
#include <cstdint>

// ---------------------------------------------------------------------------
// NonLocal2dBlock with tf32 mma.sync tensor-core GEMMs.
//   conv_cat = Wcat(256pad x 256) @ x          (B, 256, 4096)  [EPI bias]
//   thetaT   = transpose(conv[0:32])           (B, 4096, 32)
//   phi_p,g_p = maxpool2(conv[32:64],conv[64:192])
//   E  = thetaT @ phi_p        (B,4096,1024)
//   P  = softmax(E)
//   AV = g_p @ P^T             (B,128,4096)
//   y  = gamma*(out_w @ AV + out_b) + x
// ---------------------------------------------------------------------------

namespace {
constexpr int B_ = 8, C_ = 256, H_ = 64, W_ = 64;
constexpr int NPIX = H_ * W_;          // 4096
constexpr int MP   = (H_/2) * (W_/2);  // 1024
constexpr int D_   = 32, DV = 128;
constexpr int CHCAT = D_ + D_ + DV;    // 192 real channels
constexpr int CHP   = 256;             // padded to multiple of 128
}

__device__ float d_Wcat[CHP * C_];
__device__ float d_bcat[CHP];
__device__ float d_conv[(size_t)B_ * CHP * NPIX];
__device__ float d_thT [(size_t)B_ * NPIX * D_];   // theta transposed [m][k]
__device__ float d_phip[(size_t)B_ * D_ * MP];
__device__ float d_gp  [(size_t)B_ * DV * MP];
__device__ float d_att [(size_t)B_ * NPIX * MP];
__device__ float d_av  [(size_t)B_ * DV * NPIX];

// ---------------------------------------------------------------------------
__global__ void prep_weights(const float* __restrict__ tw, const float* __restrict__ tb,
                             const float* __restrict__ pw, const float* __restrict__ pb,
                             const float* __restrict__ gw, const float* __restrict__ gb)
{
    int i = blockIdx.x * blockDim.x + threadIdx.x;
    if (i < CHP * C_) {
        int ch = i / C_, k = i % C_;
        float v = 0.f;
        if      (ch < D_)      v = tw[ch * C_ + k];
        else if (ch < 2 * D_)  v = pw[(ch - D_) * C_ + k];
        else if (ch < CHCAT)   v = gw[(ch - 2 * D_) * C_ + k];
        d_Wcat[i] = v;
    }
    if (i < CHP) {
        float v = 0.f;
        if      (i < D_)      v = tb[i];
        else if (i < 2 * D_)  v = pb[i - D_];
        else if (i < CHCAT)   v = gb[i - 2 * D_];
        d_bcat[i] = v;
    }
}

// ---------------------------------------------------------------------------
__device__ __forceinline__ uint32_t tf32_bits(float x) {
    uint32_t u;
    asm("cvt.rna.tf32.f32 %0, %1;" : "=r"(u) : "f"(x));
    return u;
}
// permuted position of k within its 8-group: [0,4,1,5,2,6,3,7] -> 0..7
__device__ __forceinline__ int kcol(int kk) {
    int g = kk >> 3, i = kk & 7;
    int pos = (i < 4) ? (i << 1) : (((i - 4) << 1) | 1);
    return (g << 3) | pos;
}

// ---------------------------------------------------------------------------
// tf32 tensor-core GEMM: C[M][N] = A[M][K] @ B
//   BNK=0: B stored [K][N] (n contig, ldb=Ndim); BNK=1: B stored [N][K] (ldb=Kdim)
//   EPI: 0 plain, 1 +bias[m], 2 gamma*(acc+bias[m])+resid
// Block tile 128x64x32, 128 threads, 4 warps (2x2), warp tile 64x32.
// Mdim % 128 == 0, Ndim % 64 == 0, Kdim % 32 == 0 (true for all uses).
// ---------------------------------------------------------------------------
template<int BNK, int EPI>
__global__ __launch_bounds__(128)
void gemm_tf32(const float* __restrict__ A, const float* __restrict__ B,
               float* __restrict__ C,
               int Ndim, int Kdim,
               long long sA, long long sB, long long sC,
               const float* __restrict__ bias,
               const float* __restrict__ gamma,
               const float* __restrict__ resid, long long sR)
{
    __shared__ float As[128 * 32];     // [m][kcol] XOR-swizzled
    __shared__ float Bs[32 * 68];      // [kcol][n] ld=68

    const int bz = blockIdx.z;
    A += (size_t)bz * sA;
    B += (size_t)bz * sB;
    C += (size_t)bz * sC;
    if (EPI == 2) resid += (size_t)bz * sR;

    const int tid  = threadIdx.x;
    const int lane = tid & 31;
    const int wid  = tid >> 5;
    const int wm   = (wid >> 1) * 64;   // warp m offset (0/64)
    const int wn   = (wid & 1) * 32;    // warp n offset (0/32)
    const int r    = lane >> 2;         // 0..7
    const int q    = lane & 3;          // 0..3

    const int m0 = blockIdx.y * 128, n0 = blockIdx.x * 64;

    float acc[4][4][4];
#pragma unroll
    for (int i = 0; i < 4; i++)
#pragma unroll
        for (int j = 0; j < 4; j++)
#pragma unroll
            for (int t = 0; t < 4; t++) acc[i][j][t] = 0.f;

    for (int k0 = 0; k0 < Kdim; k0 += 32) {
        // ---- fill As: A[m][k], float4 along k ----
        {
            const int ml = tid >> 3;       // 0..15
            const int c  = tid & 7;        // float4 index
#pragma unroll
            for (int p = 0; p < 8; p++) {
                int m = ml + p * 16;
                float4 v = *(const float4*)(A + (size_t)(m0 + m) * Kdim + k0 + c * 4);
                uint32_t u0 = tf32_bits(v.x), u1 = tf32_bits(v.y);
                uint32_t u2 = tf32_bits(v.z), u3 = tf32_bits(v.w);
                int sw = (m & 3) << 3;
                int cb = (c >> 1) * 8 + (c & 1);
                As[m * 32 + ((cb + 0) ^ sw)] = __uint_as_float(u0);
                As[m * 32 + ((cb + 2) ^ sw)] = __uint_as_float(u1);
                As[m * 32 + ((cb + 4) ^ sw)] = __uint_as_float(u2);
                As[m * 32 + ((cb + 6) ^ sw)] = __uint_as_float(u3);
            }
        }
        // ---- fill Bs ----
        if (BNK == 0) {   // B[k][n], float4 along n -> vector STS
            const int kl = tid >> 4;       // 0..7
            const int nl = (tid & 15) * 4;
#pragma unroll
            for (int p = 0; p < 4; p++) {
                int k = kl + p * 8;
                float4 v = *(const float4*)(B + (size_t)(k0 + k) * Ndim + n0 + nl);
                float4 cv;
                cv.x = __uint_as_float(tf32_bits(v.x));
                cv.y = __uint_as_float(tf32_bits(v.y));
                cv.z = __uint_as_float(tf32_bits(v.z));
                cv.w = __uint_as_float(tf32_bits(v.w));
                *(float4*)&Bs[kcol(k) * 68 + nl] = cv;
            }
        } else {          // B[n][k], float4 along k -> scalar STS
            const int nl = tid >> 3;       // 0..15
            const int c  = tid & 7;
#pragma unroll
            for (int p = 0; p < 4; p++) {
                int n = nl + p * 16;
                float4 v = *(const float4*)(B + (size_t)(n0 + n) * Kdim + k0 + c * 4);
                int cb = (c >> 1) * 8 + (c & 1);
                Bs[(cb + 0) * 68 + n] = __uint_as_float(tf32_bits(v.x));
                Bs[(cb + 2) * 68 + n] = __uint_as_float(tf32_bits(v.y));
                Bs[(cb + 4) * 68 + n] = __uint_as_float(tf32_bits(v.z));
                Bs[(cb + 6) * 68 + n] = __uint_as_float(tf32_bits(v.w));
            }
        }
        __syncthreads();

        // ---- 4 x k8 mma steps ----
#pragma unroll
        for (int ks = 0; ks < 4; ks++) {
            uint32_t a[4][4];
#pragma unroll
            for (int mt = 0; mt < 4; mt++) {
                int row = wm + mt * 16 + r;
                int cA  = ((ks ^ (r & 3)) << 3) | (q << 1);
                float2 lo = *(const float2*)&As[row * 32 + cA];
                float2 hi = *(const float2*)&As[(row + 8) * 32 + cA];
                a[mt][0] = __float_as_uint(lo.x);   // (r,   q)
                a[mt][1] = __float_as_uint(hi.x);   // (r+8, q)
                a[mt][2] = __float_as_uint(lo.y);   // (r,   q+4)
                a[mt][3] = __float_as_uint(hi.y);   // (r+8, q+4)
            }
            uint32_t b[4][2];
#pragma unroll
            for (int nt = 0; nt < 4; nt++) {
                int nn = wn + nt * 8 + r;
                b[nt][0] = __float_as_uint(Bs[(ks * 8 + 2 * q + 0) * 68 + nn]); // k=q
                b[nt][1] = __float_as_uint(Bs[(ks * 8 + 2 * q + 1) * 68 + nn]); // k=q+4
            }
#pragma unroll
            for (int mt = 0; mt < 4; mt++)
#pragma unroll
                for (int nt = 0; nt < 4; nt++) {
                    asm volatile(
                        "mma.sync.aligned.m16n8k8.row.col.f32.tf32.tf32.f32 "
                        "{%0,%1,%2,%3}, {%4,%5,%6,%7}, {%8,%9}, {%0,%1,%2,%3};\n"
                        : "+f"(acc[mt][nt][0]), "+f"(acc[mt][nt][1]),
                          "+f"(acc[mt][nt][2]), "+f"(acc[mt][nt][3])
                        : "r"(a[mt][0]), "r"(a[mt][1]), "r"(a[mt][2]), "r"(a[mt][3]),
                          "r"(b[nt][0]), "r"(b[nt][1]));
                }
        }
        __syncthreads();
    }

    // ---- epilogue ----
    float gm = 0.f;
    if (EPI == 2) gm = __ldg(gamma);
#pragma unroll
    for (int mt = 0; mt < 4; mt++) {
#pragma unroll
        for (int half = 0; half < 2; half++) {
            int mrow = m0 + wm + mt * 16 + r + half * 8;
            float bv = 0.f;
            if (EPI >= 1) bv = __ldg(&bias[mrow]);
#pragma unroll
            for (int nt = 0; nt < 4; nt++) {
                int ncol = n0 + wn + nt * 8 + 2 * q;
                float2 v;
                v.x = acc[mt][nt][half * 2 + 0];
                v.y = acc[mt][nt][half * 2 + 1];
                if (EPI >= 1) { v.x += bv; v.y += bv; }
                if (EPI == 2) {
                    float2 xr = *(const float2*)(resid + (size_t)mrow * Ndim + ncol);
                    v.x = gm * v.x + xr.x;
                    v.y = gm * v.y + xr.y;
                }
                *(float2*)(C + (size_t)mrow * Ndim + ncol) = v;
            }
        }
    }
}

// ---------------------------------------------------------------------------
// transpose theta: d_thT[b][m][k] = d_conv[b][k][m], k<32
// ---------------------------------------------------------------------------
__global__ void transpose_theta()
{
    __shared__ float s[32][33];
    int b  = blockIdx.z;
    int m0 = blockIdx.x * 32;
    int tx = threadIdx.x, ty = threadIdx.y;
    const float* src = d_conv + (size_t)b * CHP * NPIX;
    float* dst = d_thT + (size_t)b * NPIX * D_;
#pragma unroll
    for (int i = 0; i < 4; i++) {
        int k = ty + i * 8;
        s[k][tx] = src[(size_t)k * NPIX + m0 + tx];
    }
    __syncthreads();
#pragma unroll
    for (int i = 0; i < 4; i++) {
        int mm = ty + i * 8;
        dst[(size_t)(m0 + mm) * D_ + tx] = s[tx][mm];
    }
}

// ---------------------------------------------------------------------------
__global__ void pool_kernel()
{
    int i = blockIdx.x * blockDim.x + threadIdx.x;
    constexpr int total = B_ * (D_ + DV) * MP;
    if (i >= total) return;
    int m  = i % MP;
    int rr = i / MP;
    int ch = rr % (D_ + DV);
    int b  = rr / (D_ + DV);
    int mh = m >> 5, mw = m & 31;
    const float* src; float* dst;
    if (ch < D_) {
        src = d_conv + ((size_t)b * CHP + D_ + ch) * NPIX;
        dst = d_phip + ((size_t)b * D_ + ch) * MP;
    } else {
        src = d_conv + ((size_t)b * CHP + 2 * D_ + (ch - D_)) * NPIX;
        dst = d_gp   + ((size_t)b * DV + (ch - D_)) * MP;
    }
    int p0 = (mh * 2) * W_ + mw * 2;
    dst[m] = fmaxf(fmaxf(src[p0], src[p0 + 1]),
                   fmaxf(src[p0 + W_], src[p0 + W_ + 1]));
}

// ---------------------------------------------------------------------------
__global__ __launch_bounds__(128)
void softmax_kernel()
{
    float* p = d_att + (size_t)blockIdx.x * MP;
    int t = threadIdx.x;
    float4* pv = (float4*)p;
    float4 v0 = pv[t];
    float4 v1 = pv[t + 128];

    float m = fmaxf(fmaxf(fmaxf(v0.x, v0.y), fmaxf(v0.z, v0.w)),
                    fmaxf(fmaxf(v1.x, v1.y), fmaxf(v1.z, v1.w)));
#pragma unroll
    for (int o = 16; o; o >>= 1) m = fmaxf(m, __shfl_xor_sync(0xffffffffu, m, o));
    __shared__ float redm[4], reds[4];
    if ((t & 31) == 0) redm[t >> 5] = m;
    __syncthreads();
    m = fmaxf(fmaxf(redm[0], redm[1]), fmaxf(redm[2], redm[3]));

    v0.x = __expf(v0.x - m); v0.y = __expf(v0.y - m);
    v0.z = __expf(v0.z - m); v0.w = __expf(v0.w - m);
    v1.x = __expf(v1.x - m); v1.y = __expf(v1.y - m);
    v1.z = __expf(v1.z - m); v1.w = __expf(v1.w - m);

    float s = v0.x + v0.y + v0.z + v0.w + v1.x + v1.y + v1.z + v1.w;
#pragma unroll
    for (int o = 16; o; o >>= 1) s += __shfl_xor_sync(0xffffffffu, s, o);
    if ((t & 31) == 0) reds[t >> 5] = s;
    __syncthreads();
    s = reds[0] + reds[1] + reds[2] + reds[3];

    float inv = 1.f / s;
    v0.x *= inv; v0.y *= inv; v0.z *= inv; v0.w *= inv;
    v1.x *= inv; v1.y *= inv; v1.z *= inv; v1.w *= inv;
    pv[t] = v0;
    pv[t + 128] = v1;
}

// ---------------------------------------------------------------------------
extern "C" void kernel_launch(void* const* d_in, const int* in_sizes, int n_in,
                              void* d_out, int out_size)
{
    const float* x     = (const float*)d_in[0];
    const float* tw    = (const float*)d_in[1];
    const float* tb    = (const float*)d_in[2];
    const float* pw    = (const float*)d_in[3];
    const float* pb    = (const float*)d_in[4];
    const float* gw    = (const float*)d_in[5];
    const float* gb    = (const float*)d_in[6];
    const float* ow    = (const float*)d_in[7];
    const float* ob    = (const float*)d_in[8];
    const float* gamma = (const float*)d_in[9];
    float* out = (float*)d_out;

    float *pWcat, *pbcat, *pconv, *pthT, *pphip, *pgp, *patt, *pav;
    cudaGetSymbolAddress((void**)&pWcat, d_Wcat);
    cudaGetSymbolAddress((void**)&pbcat, d_bcat);
    cudaGetSymbolAddress((void**)&pconv, d_conv);
    cudaGetSymbolAddress((void**)&pthT,  d_thT);
    cudaGetSymbolAddress((void**)&pphip, d_phip);
    cudaGetSymbolAddress((void**)&pgp,   d_gp);
    cudaGetSymbolAddress((void**)&patt,  d_att);
    cudaGetSymbolAddress((void**)&pav,   d_av);

    // K0: pack + pad concatenated QKV weights
    prep_weights<<<(CHP * C_ + 255) / 256, 256>>>(tw, tb, pw, pb, gw, gb);

    // K1: conv_cat = Wcat @ x + bcat   M=256(pad) N=4096 K=256
    {
        dim3 g(NPIX / 64, CHP / 128, B_);
        gemm_tf32<0, 1><<<g, 128>>>(pWcat, x, pconv, NPIX, C_,
                                    0LL, (long long)C_ * NPIX, (long long)CHP * NPIX,
                                    pbcat, nullptr, nullptr, 0LL);
    }

    // K2a: transpose theta; K2b: pool phi/g
    {
        dim3 g(NPIX / 32, 1, B_);
        transpose_theta<<<g, dim3(32, 8)>>>();
        int tot = B_ * (D_ + DV) * MP;
        pool_kernel<<<(tot + 255) / 256, 256>>>();
    }

    // K3: E = thetaT @ phi_p   M=4096 N=1024 K=32
    {
        dim3 g(MP / 64, NPIX / 128, B_);
        gemm_tf32<0, 0><<<g, 128>>>(pthT, pphip, patt, MP, D_,
                                    (long long)NPIX * D_, (long long)D_ * MP,
                                    (long long)NPIX * MP,
                                    nullptr, nullptr, nullptr, 0LL);
    }

    // K4: softmax rows
    softmax_kernel<<<B_ * NPIX, 128>>>();

    // K5: AV = g_p @ P^T   M=128 N=4096 K=1024  (B stored [N][K])
    {
        dim3 g(NPIX / 64, DV / 128, B_);
        gemm_tf32<1, 0><<<g, 128>>>(pgp, patt, pav, NPIX, MP,
                                    (long long)DV * MP, (long long)NPIX * MP,
                                    (long long)DV * NPIX,
                                    nullptr, nullptr, nullptr, 0LL);
    }

    // K6: y = gamma*(out_w @ AV + out_b) + x   M=256 N=4096 K=128
    {
        dim3 g(NPIX / 64, C_ / 128, B_);
        gemm_tf32<0, 2><<<g, 128>>>(ow, pav, out, NPIX, DV,
                                    0LL, (long long)DV * NPIX, (long long)C_ * NPIX,
                                    ob, gamma, x, (long long)C_ * NPIX);
    }
}